// round 3
// baseline (speedup 1.0000x reference)
#include <cuda_runtime.h>
#include <cstdint>

#define MAXB 64
#define MAXP 8800
#define MAXN 64

// ---------------- scratch (device globals) ----------------
__device__ int                g_meta[MAXB * MAXP];    // bti | (pos0<<8)
__device__ float              g_lsem[MAXB * MAXP];    // logsumexp per anchor
__device__ float              g_lossc[MAXB * MAXP];   // loss_c (0 for pos)
__device__ unsigned long long g_key[MAXB * MAXN];     // per-GT best prior key
__device__ int                g_numpos[MAXB];
__device__ double             g_acc[3];               // loc, ce_pos, ce_neg

// ---------------- helpers ----------------
__device__ __forceinline__ void cp16(uint32_t s, const void* g) {
    asm volatile("cp.async.cg.shared.global [%0], [%1], 16;" :: "r"(s), "l"(g));
}

__device__ __forceinline__ double warpSumD(double v) {
#pragma unroll
    for (int o = 16; o; o >>= 1) v += __shfl_down_sync(0xFFFFFFFFu, v, o);
    return v;
}
__device__ __forceinline__ int warpSumI(int v) {
#pragma unroll
    for (int o = 16; o; o >>= 1) v += __shfl_down_sync(0xFFFFFFFFu, v, o);
    return v;
}

__device__ int blockSumI(int v, int* sh) {
    __syncthreads();
    int lane = threadIdx.x & 31, wid = threadIdx.x >> 5;
    v = warpSumI(v);
    if (lane == 0) sh[wid] = v;
    __syncthreads();
    if (wid == 0) {
        int nw = (blockDim.x + 31) >> 5;
        int x = (lane < nw) ? sh[lane] : 0;
        x = warpSumI(x);
        if (lane == 0) sh[0] = x;
    }
    __syncthreads();
    return sh[0];
}

__device__ double blockSumD(double v, double* sh) {
    __syncthreads();
    int lane = threadIdx.x & 31, wid = threadIdx.x >> 5;
    v = warpSumD(v);
    if (lane == 0) sh[wid] = v;
    __syncthreads();
    if (wid == 0) {
        int nw = (blockDim.x + 31) >> 5;
        double x = (lane < nw) ? sh[lane] : 0.0;
        x = warpSumD(x);
        if (lane == 0) sh[0] = x;
    }
    __syncthreads();
    return sh[0];
}

// smooth-L1 of (loc row) vs encoded gt for prior pr. Used identically in
// k_fused and k_corr so contributions cancel exactly.
__device__ __forceinline__ float sl1_loc(float4 pr, float4 lr, const float* gt) {
    float t0 = ((gt[0] + gt[2]) * 0.5f - pr.x) / (0.1f * pr.z);
    float t1 = ((gt[1] + gt[3]) * 0.5f - pr.y) / (0.1f * pr.w);
    float t2 = __logf((gt[2] - gt[0]) / pr.z) / 0.2f;
    float t3 = __logf((gt[3] - gt[1]) / pr.w) / 0.2f;
    float l[4] = {lr.x, lr.y, lr.z, lr.w};
    float t[4] = {t0, t1, t2, t3};
    float acc = 0.0f;
#pragma unroll
    for (int i = 0; i < 4; i++) {
        float d = fabsf(l[i] - t[i]);
        acc += (d < 1.0f) ? 0.5f * d * d : d - 0.5f;
    }
    return acc;
}

// ---------------- kernel 0: init ----------------
__global__ void k_init(int B, int NMAX) {
    int i = blockIdx.x * blockDim.x + threadIdx.x;
    if (i < B * NMAX) g_key[i] = 0xFFFFFFFFull;  // iou=0, p=0 baseline
    if (i < B) g_numpos[i] = 0;
    if (i < 3) g_acc[i] = 0.0;
}

// ---------------- kernel 1: fused match + CE + loc loss ----------------
// grid: (ceil(P/256), B) x 256. cp.async streams the conf tile while the
// IoU match loop runs; CE uses match result from registers.
template <int C>
__global__ void __launch_bounds__(256) k_fused(
        const float* __restrict__ conf, const float* __restrict__ loc,
        const float* __restrict__ priors, const float* __restrict__ labels,
        const int* __restrict__ obj_count, int P, int NMAX) {
    __shared__ float shc[256 * C + 4];
    __shared__ float4 sh_box[MAXN];
    __shared__ float  sh_area[MAXN];
    __shared__ float  sh_cls[MAXN];
    __shared__ unsigned long long sh_key[MAXN];
    __shared__ unsigned int sh_best[MAXN];

    int tid = threadIdx.x;
    int b = blockIdx.y;
    int p0 = blockIdx.x * 256;
    int cnt = min(256, P - p0);
    int p = p0 + tid;

    // --- start async conf staging (16B chunks from aligned-down start) ---
    size_t base_byte = ((size_t)b * P + p0) * C * 4;
    size_t gstart = base_byte & ~(size_t)15;
    int lead = (int)((base_byte - gstart) >> 2);       // 0..3 floats
    int n16 = ((cnt * C + lead) * 4 + 15) >> 4;
    uint32_t sb = (uint32_t)__cvta_generic_to_shared(shc);
    const char* gp = (const char*)conf + gstart;
    for (int i = tid; i < n16; i += 256)
        cp16(sb + i * 16, gp + (size_t)i * 16);
    asm volatile("cp.async.commit_group;");

    // --- stage GT boxes ---
    int nv = obj_count[b];
    if (nv > NMAX) nv = NMAX;
    for (int n = tid; n < nv; n += 256) {
        const float* g = labels + ((size_t)b * NMAX + n) * 5;
        float x0 = g[0], y0 = g[1], x1 = g[2], y1 = g[3];
        sh_box[n] = make_float4(x0, y0, x1, y1);
        sh_area[n] = (x1 - x0) * (y1 - y0);
        sh_cls[n] = g[4];
        sh_key[n] = 0ull;
        sh_best[n] = 0u;
    }
    __syncthreads();

    // --- match loop (runs under the cp.async loads) ---
    float bestI = -1.0f, bestU = 1.0f;
    int bestN = 0;
    float4 pr = make_float4(0, 0, 1, 1);
    if (p < P) {
        pr = reinterpret_cast<const float4*>(priors)[p];
        float px0 = pr.x - 0.5f * pr.z, py0 = pr.y - 0.5f * pr.w;
        float px1 = pr.x + 0.5f * pr.z, py1 = pr.y + 0.5f * pr.w;
        float ab = pr.z * pr.w;
        for (int n = 0; n < nv; n++) {
            float4 g = sh_box[n];
            float iw = fminf(px1, g.z) - fmaxf(px0, g.x);
            float ih = fminf(py1, g.w) - fmaxf(py0, g.y);
            if (fminf(iw, ih) > 0.0f) {
                float inter = iw * ih;
                float uni = sh_area[n] + ab - inter;
                if (inter * bestU > bestI * uni) { bestI = inter; bestU = uni; bestN = n; }
                float cur = __uint_as_float(sh_best[n]);
                if (inter > cur * uni) {
                    float iou = inter / uni;
                    unsigned int ib = __float_as_uint(iou);
                    atomicMax(&sh_best[n], ib);
                    unsigned long long key =
                        ((unsigned long long)ib << 32) |
                        (unsigned long long)(0xFFFFFFFFu - (unsigned)p);
                    atomicMax(&sh_key[n], key);
                }
            }
        }
    }
    __syncthreads();
    for (int n = tid; n < nv; n += 256)
        if (sh_key[n]) atomicMax(&g_key[(size_t)b * NMAX + n], sh_key[n]);

    // --- wait for conf, then CE + positive losses ---
    asm volatile("cp.async.wait_group 0;" ::: "memory");
    __syncthreads();

    double myloc = 0.0, myce = 0.0;
    int mypos = 0;
    if (p < P) {
        size_t bp = (size_t)b * P + p;
        bool pos0 = (bestI > 0.0f) && (bestI >= 0.5f * bestU);
        int ct = pos0 ? ((int)sh_cls[bestN] + 1) : 0;

        const float* vv = shc + lead + tid * C;
        float r[C];
#pragma unroll
        for (int c = 0; c < C; c++) r[c] = vv[c];
        float m = r[0];
#pragma unroll
        for (int c = 1; c < C; c++) m = fmaxf(m, r[c]);
        float s = 0.0f, tgt = 0.0f;
#pragma unroll
        for (int c = 0; c < C; c++) {
            s += __expf(r[c] - m);
            if (c == ct) tgt = r[c];
        }
        float lsem = __logf(s) + m;
        float ce = lsem - tgt;

        g_lsem[bp] = lsem;
        g_lossc[bp] = pos0 ? 0.0f : ce;
        g_meta[bp] = bestN | (pos0 ? 256 : 0);

        if (pos0) {
            mypos = 1;
            myce = (double)ce;
            float4 g = sh_box[bestN];
            float gt[4] = {g.x, g.y, g.z, g.w};
            float4 lr = reinterpret_cast<const float4*>(loc)[bp];
            myloc = (double)sl1_loc(pr, lr, gt);
        }
    }

    __shared__ double shd0[8], shd1[8];
    __shared__ int shi[8];
    int lane = tid & 31, wid = tid >> 5;
    myloc = warpSumD(myloc);
    myce = warpSumD(myce);
    mypos = warpSumI(mypos);
    if (lane == 0) { shd0[wid] = myloc; shd1[wid] = myce; shi[wid] = mypos; }
    __syncthreads();
    if (tid == 0) {
        double a = 0.0, c2 = 0.0; int cp = 0;
        for (int w = 0; w < 8; w++) { a += shd0[w]; c2 += shd1[w]; cp += shi[w]; }
        if (a != 0.0) atomicAdd(&g_acc[0], a);
        if (c2 != 0.0) atomicAdd(&g_acc[1], c2);
        if (cp) atomicAdd(&g_numpos[b], cp);
    }
}

// ---------------- kernel 2: override correction ----------------
// grid: B blocks x 64. Winner n per prior (max n = last-wins), apply deltas.
template <int C>
__global__ void k_corr(const float* __restrict__ conf, const float* __restrict__ loc,
                       const float* __restrict__ priors, const float* __restrict__ labels,
                       const int* __restrict__ obj_count, int P, int NMAX) {
    int b = blockIdx.x, n = threadIdx.x;
    __shared__ unsigned int sp[MAXN];
    int nv = obj_count[b];
    if (nv > NMAX) nv = NMAX;

    unsigned int p = 0xFFFFFFFFu;
    if (n < nv) {
        unsigned long long key = g_key[(size_t)b * NMAX + n];
        p = 0xFFFFFFFFu - (unsigned int)(key & 0xFFFFFFFFull);
    }
    if (n < MAXN) sp[n] = (n < nv) ? p : 0xFFFFFFFFu;
    __syncthreads();

    bool win = (n < nv);
    if (win)
        for (int m = n + 1; m < nv; m++)
            if (sp[m] == p) { win = false; break; }

    double dl = 0.0, dc = 0.0;
    int dp = 0;
    if (win) {
        size_t bp = (size_t)b * P + p;
        int meta = g_meta[bp];
        int bti0 = meta & 255;
        bool pos0 = (meta & 256) != 0;
        float lsem = g_lsem[bp];
        float4 prr = reinterpret_cast<const float4*>(priors)[p];
        float4 lr = reinterpret_cast<const float4*>(loc)[bp];

        const float* gtN = labels + ((size_t)b * NMAX + n) * 5;
        int ctN = (int)gtN[4] + 1;
        float ce_new = lsem - conf[bp * C + ctN];
        float gN[4] = {gtN[0], gtN[1], gtN[2], gtN[3]};
        float loc_new = sl1_loc(prr, lr, gN);

        float ce_old = 0.0f, loc_old = 0.0f;
        if (pos0) {
            const float* gt0 = labels + ((size_t)b * NMAX + bti0) * 5;
            int ct0 = (int)gt0[4] + 1;
            ce_old = lsem - conf[bp * C + ct0];
            float g0[4] = {gt0[0], gt0[1], gt0[2], gt0[3]};
            loc_old = sl1_loc(prr, lr, g0);
        } else {
            dp = 1;
            g_lossc[bp] = 0.0f;   // was neg; now forced pos
        }
        dl = (double)loc_new - (double)loc_old;
        dc = (double)ce_new - (double)ce_old;
    }

    dl = warpSumD(dl);
    dc = warpSumD(dc);
    dp = warpSumI(dp);
    __shared__ double w0[2], w1[2];
    __shared__ int wi[2];
    int lane = threadIdx.x & 31, wid = threadIdx.x >> 5;
    if (lane == 0) { w0[wid] = dl; w1[wid] = dc; wi[wid] = dp; }
    __syncthreads();
    if (threadIdx.x == 0) {
        double a = w0[0] + w0[1], c2 = w1[0] + w1[1];
        int q = wi[0] + wi[1];
        if (a != 0.0) atomicAdd(&g_acc[0], a);
        if (c2 != 0.0) atomicAdd(&g_acc[1], c2);
        if (q) atomicAdd(&g_numpos[b], q);
    }
}

// ---------------- kernel 3: radix top-k negative selection (tie-exact) ----------------
// grid: B blocks x 1024
__global__ void k_select(int P) {
    int b = blockIdx.x;
    __shared__ unsigned int sv[MAXP];
    __shared__ int hist[2048];
    __shared__ int s_ri[32];
    __shared__ double s_rd[32];
    __shared__ int s_sel;
    int tid = threadIdx.x, nt = blockDim.x;
    int lane = tid & 31;

    for (int i = tid; i < P; i += nt)
        sv[i] = __float_as_uint(g_lossc[(size_t)b * P + i]);

    int npos = g_numpos[b];
    int k = 3 * npos;
    if (k > P - 1) k = P - 1;
    __syncthreads();
    if (k <= 0) return;

    unsigned int prefix = 0;
    int kk = k;
    const int bitsArr[3] = {11, 11, 10};
    const int shiftArr[3] = {21, 10, 0};
    int iters = (P + nt - 1) / nt;

    for (int r = 0; r < 3; r++) {
        int bits = bitsArr[r], shift = shiftArr[r];
        int nb = 1 << bits;
        for (int i = tid; i < nb; i += nt) hist[i] = 0;
        if (tid == 0) s_sel = 0;
        __syncthreads();

        for (int j = 0; j < iters; j++) {
            int i = tid + j * nt;
            bool valid = (i < P);
            unsigned int v = valid ? sv[i] : 0u;
            unsigned int hi = (r == 0) ? 0u : (v >> (shift + bits));
            valid = valid && (hi == prefix);
            unsigned int bm = __ballot_sync(0xFFFFFFFFu, valid);
            if (valid) {
                int bin = (v >> shift) & (nb - 1);
                unsigned int mm = __match_any_sync(bm, bin);
                int leader = __ffs(mm) - 1;
                if (lane == leader) atomicAdd(&hist[bin], __popc(mm));
            }
        }
        __syncthreads();

        // inclusive suffix scan over hist[0..nb)
        for (int off = 1; off < nb; off <<= 1) {
            int i0 = tid, i1 = tid + nt;
            int v0 = 0, v1 = 0;
            if (i0 < nb) v0 = hist[i0] + ((i0 + off < nb) ? hist[i0 + off] : 0);
            if (i1 < nb) v1 = hist[i1] + ((i1 + off < nb) ? hist[i1 + off] : 0);
            __syncthreads();
            if (i0 < nb) hist[i0] = v0;
            if (i1 < nb) hist[i1] = v1;
            __syncthreads();
        }

        if (tid < nb && hist[tid] >= kk) atomicMax(&s_sel, tid);
        {
            int i1 = tid + nt;
            if (i1 < nb && hist[i1] >= kk) atomicMax(&s_sel, i1);
        }
        __syncthreads();
        int d = s_sel;
        int above = (d + 1 < nb) ? hist[d + 1] : 0;
        kk -= above;
        prefix = (prefix << bits) | (unsigned int)d;
        __syncthreads();
    }

    unsigned int T = prefix;
    int c1 = 0;
    double s1 = 0.0;
    for (int i = tid; i < P; i += nt) {
        unsigned int v = sv[i];
        if (v > T) { c1++; s1 += (double)__uint_as_float(v); }
    }
    c1 = blockSumI(c1, s_ri);
    s1 = blockSumD(s1, s_rd);
    if (tid == 0)
        atomicAdd(&g_acc[2], s1 + (double)(k - c1) * (double)__uint_as_float(T));
}

// ---------------- kernel 4: finalize ----------------
__global__ void k_final(float* out, int B) {
    if (threadIdx.x == 0) {
        long long N = 0;
        for (int b = 0; b < B; b++) N += g_numpos[b];
        double Nd = (double)N;
        out[0] = (float)(g_acc[0] / Nd);
        out[1] = (float)((g_acc[1] + g_acc[2]) / Nd);
    }
}

// ---------------- launch ----------------
extern "C" void kernel_launch(void* const* d_in, const int* in_sizes, int n_in,
                              void* d_out, int out_size) {
    const float* conf   = (const float*)d_in[0];
    const float* loc    = (const float*)d_in[1];
    const float* priors = (const float*)d_in[2];
    const float* labels = (const float*)d_in[3];
    const int*   obj    = (const int*)d_in[4];

    int P = in_sizes[2] / 4;
    int B = in_sizes[4];
    int NMAX = in_sizes[3] / (B * 5);

    k_init<<<(B * NMAX + 255) / 256, 256>>>(B, NMAX);

    dim3 gf((P + 255) / 256, B);
    k_fused<21><<<gf, 256>>>(conf, loc, priors, labels, obj, P, NMAX);

    k_corr<21><<<B, 64>>>(conf, loc, priors, labels, obj, P, NMAX);

    k_select<<<B, 1024>>>(P);
    k_final<<<1, 32>>>((float*)d_out, B);
}

// round 5
// speedup vs baseline: 1.4262x; 1.4262x over previous
#include <cuda_runtime.h>
#include <cstdint>

#define MAXB 64
#define MAXP 8800
#define MAXN 64

// ---------------- scratch (device globals) ----------------
__device__ int                g_bti[MAXB * MAXP];     // best_truth_idx
__device__ int                g_pos0[MAXB * MAXP];    // iou >= 0.5 flag
__device__ int                g_ovr[MAXB * MAXP];     // override: n+1, 0 = none
__device__ float              g_lossc[MAXB * MAXP];   // loss_c (0 for pos)
__device__ unsigned long long g_key[MAXB * MAXN];     // per-GT best prior key
__device__ int                g_numpos[MAXB];
__device__ int                g_bdone[MAXB];          // match completion per batch
__device__ int                g_done;                 // select completion
__device__ double             g_acc[3];               // loc, ce_pos, ce_neg

// ---------------- reductions ----------------
__device__ __forceinline__ double warpSumD(double v) {
#pragma unroll
    for (int o = 16; o; o >>= 1) v += __shfl_down_sync(0xFFFFFFFFu, v, o);
    return v;
}
__device__ __forceinline__ int warpSumI(int v) {
#pragma unroll
    for (int o = 16; o; o >>= 1) v += __shfl_down_sync(0xFFFFFFFFu, v, o);
    return v;
}
// inclusive suffix sum within warp: result(lane) = sum over lanes >= lane
__device__ __forceinline__ int warpSufI(int v) {
    int lane = threadIdx.x & 31;
#pragma unroll
    for (int o = 1; o < 32; o <<= 1) {
        int t = __shfl_down_sync(0xFFFFFFFFu, v, o);
        if (lane + o < 32) v += t;
    }
    return v;
}

__device__ int blockSumI(int v, int* sh) {
    __syncthreads();
    int lane = threadIdx.x & 31, wid = threadIdx.x >> 5;
    v = warpSumI(v);
    if (lane == 0) sh[wid] = v;
    __syncthreads();
    if (wid == 0) {
        int nw = (blockDim.x + 31) >> 5;
        int x = (lane < nw) ? sh[lane] : 0;
        x = warpSumI(x);
        if (lane == 0) sh[0] = x;
    }
    __syncthreads();
    return sh[0];
}

__device__ double blockSumD(double v, double* sh) {
    __syncthreads();
    int lane = threadIdx.x & 31, wid = threadIdx.x >> 5;
    v = warpSumD(v);
    if (lane == 0) sh[wid] = v;
    __syncthreads();
    if (wid == 0) {
        int nw = (blockDim.x + 31) >> 5;
        double x = (lane < nw) ? sh[lane] : 0.0;
        x = warpSumD(x);
        if (lane == 0) sh[0] = x;
    }
    __syncthreads();
    return sh[0];
}

// ---------------- kernel 0: init ----------------
__global__ void k_init(int B, int NMAX) {
    int i = blockIdx.x * blockDim.x + threadIdx.x;
    if (i < B * NMAX) g_key[i] = 0xFFFFFFFFull;  // iou=0, p=0 baseline
    if (i < B) { g_numpos[i] = 0; g_bdone[i] = 0; }
    if (i < 3) g_acc[i] = 0.0;
    if (i == 0) g_done = 0;
}

// ---------------- kernel 1: matching + fused override ----------------
// grid: (ceil(P/256), B) x 256; last block per batch applies overrides.
__global__ void k_match(const float* __restrict__ priors,
                        const float* __restrict__ labels,
                        const int* __restrict__ obj_count,
                        int P, int NMAX) {
    int b = blockIdx.y;
    int p = blockIdx.x * blockDim.x + threadIdx.x;

    __shared__ float4 sh_box[MAXN];
    __shared__ float  sh_area[MAXN];
    __shared__ unsigned long long sh_key[MAXN];
    __shared__ unsigned int sh_best[MAXN];
    __shared__ int s_last;

    int nv = obj_count[b];
    if (nv > NMAX) nv = NMAX;

    for (int n = threadIdx.x; n < nv; n += blockDim.x) {
        const float* g = labels + ((size_t)b * NMAX + n) * 5;
        float x0 = g[0], y0 = g[1], x1 = g[2], y1 = g[3];
        sh_box[n] = make_float4(x0, y0, x1, y1);
        sh_area[n] = (x1 - x0) * (y1 - y0);
        sh_key[n] = 0ull;
        sh_best[n] = 0u;
    }
    __syncthreads();

    if (p < P) {
        float4 pr = reinterpret_cast<const float4*>(priors)[p];
        float px0 = pr.x - 0.5f * pr.z, py0 = pr.y - 0.5f * pr.w;
        float px1 = pr.x + 0.5f * pr.z, py1 = pr.y + 0.5f * pr.w;
        float ab = pr.z * pr.w;

        float bestI = -1.0f, bestU = 1.0f;
        int bestN = 0;

        for (int n = 0; n < nv; n++) {
            float4 g = sh_box[n];
            float iw = fminf(px1, g.z) - fmaxf(px0, g.x);
            float ih = fminf(py1, g.w) - fmaxf(py0, g.y);
            if (fminf(iw, ih) > 0.0f) {
                float inter = iw * ih;
                float uni = sh_area[n] + ab - inter;
                if (inter * bestU > bestI * uni) { bestI = inter; bestU = uni; bestN = n; }
                float cur = __uint_as_float(sh_best[n]);
                if (inter > cur * uni) {
                    float iou = inter / uni;
                    unsigned int ib = __float_as_uint(iou);
                    atomicMax(&sh_best[n], ib);
                    unsigned long long key =
                        ((unsigned long long)ib << 32) |
                        (unsigned long long)(0xFFFFFFFFu - (unsigned)p);
                    atomicMax(&sh_key[n], key);
                }
            }
        }
        size_t bp = (size_t)b * P + p;
        g_bti[bp] = bestN;
        g_pos0[bp] = (bestI > 0.0f && bestI >= 0.5f * bestU) ? 1 : 0;
        g_ovr[bp] = 0;
    }
    __syncthreads();
    for (int n = threadIdx.x; n < nv; n += blockDim.x)
        if (sh_key[n]) atomicMax(&g_key[(size_t)b * NMAX + n], sh_key[n]);

    // elect last block of this batch to apply overrides
    if (threadIdx.x == 0) {
        __threadfence();
        s_last = (atomicAdd(&g_bdone[b], 1) == (int)gridDim.x - 1) ? 1 : 0;
    }
    __syncthreads();
    if (s_last && threadIdx.x < nv) {
        unsigned long long key = g_key[(size_t)b * NMAX + threadIdx.x];
        unsigned int pp = 0xFFFFFFFFu - (unsigned int)(key & 0xFFFFFFFFull);
        atomicMax(&g_ovr[(size_t)b * P + pp], threadIdx.x + 1);
    }
}

// ---------------- kernel 2: per-anchor losses (smem-staged, 2 anchors/thread) ----------------
// grid: (ceil(P/256), B) x 128
template <int C>
__global__ void __launch_bounds__(128) k_loss(
        const float* __restrict__ conf, const float* __restrict__ loc,
        const float* __restrict__ priors, const float* __restrict__ labels,
        int P, int NMAX) {
    __shared__ float4 shc4[(256 * C + 8) / 4];
    __shared__ float4 sh_box[MAXN];
    __shared__ float  sh_cls[MAXN];
    float* shc = (float*)shc4;

    int tid = threadIdx.x;
    int b = blockIdx.y;
    int p0 = blockIdx.x * 256;
    int cnt = min(256, P - p0);

    // stage conf tile (coalesced float4 from 16B-aligned-down start)
    size_t base_byte = ((size_t)b * P + p0) * C * 4;
    size_t gstart = base_byte & ~(size_t)15;
    int lead = (int)((base_byte - gstart) >> 2);
    int nfl = lead + cnt * C;
    int nf4 = nfl >> 2, rem = nfl & 3;
    const float4* s4 = reinterpret_cast<const float4*>((const char*)conf + gstart);
    for (int i = tid; i < nf4; i += 128) shc4[i] = s4[i];
    if (tid < rem) shc[nf4 * 4 + tid] = ((const float*)s4)[nf4 * 4 + tid];

    // stage gt boxes
    for (int n = tid; n < NMAX; n += 128) {
        const float* g = labels + ((size_t)b * NMAX + n) * 5;
        sh_box[n] = make_float4(g[0], g[1], g[2], g[3]);
        sh_cls[n] = g[4];
    }
    __syncthreads();

    double myloc = 0.0, myce = 0.0;
    int mypos = 0;

#pragma unroll
    for (int half = 0; half < 2; half++) {
        int row = tid + half * 128;
        int p = p0 + row;
        if (p >= P) break;
        size_t bp = (size_t)b * P + p;

        int ovr = g_ovr[bp];
        int n;  bool pos;
        if (ovr > 0) { n = ovr - 1; pos = true; }
        else         { n = g_bti[bp]; pos = (g_pos0[bp] != 0); }
        int ct = pos ? ((int)sh_cls[n] + 1) : 0;

        const float* vv = shc + lead + row * C;
        float m = vv[0];
#pragma unroll
        for (int c = 1; c < C; c++) m = fmaxf(m, vv[c]);
        float s = 0.0f;
#pragma unroll
        for (int c = 0; c < C; c++) s += __expf(vv[c] - m);
        float ce = __logf(s) + m - vv[ct];
        g_lossc[bp] = pos ? 0.0f : ce;

        if (pos) {
            mypos++;
            myce += (double)ce;
            float4 pr = reinterpret_cast<const float4*>(priors)[p];
            float4 g = sh_box[n];
            float t0 = ((g.x + g.z) * 0.5f - pr.x) / (0.1f * pr.z);
            float t1 = ((g.y + g.w) * 0.5f - pr.y) / (0.1f * pr.w);
            float t2 = __logf((g.z - g.x) / pr.z) / 0.2f;
            float t3 = __logf((g.w - g.y) / pr.w) / 0.2f;
            float4 lr = reinterpret_cast<const float4*>(loc)[bp];
            float t[4] = {t0, t1, t2, t3};
            float l[4] = {lr.x, lr.y, lr.z, lr.w};
            float acc = 0.0f;
#pragma unroll
            for (int i = 0; i < 4; i++) {
                float d = fabsf(l[i] - t[i]);
                acc += (d < 1.0f) ? 0.5f * d * d : d - 0.5f;
            }
            myloc += (double)acc;
        }
    }

    __shared__ double shd0[4], shd1[4];
    __shared__ int shi[4];
    int lane = tid & 31, wid = tid >> 5;
    myloc = warpSumD(myloc);
    myce = warpSumD(myce);
    mypos = warpSumI(mypos);
    if (lane == 0) { shd0[wid] = myloc; shd1[wid] = myce; shi[wid] = mypos; }
    __syncthreads();
    if (tid == 0) {
        double a = 0.0, c2 = 0.0; int cp = 0;
        for (int w = 0; w < 4; w++) { a += shd0[w]; c2 += shd1[w]; cp += shi[w]; }
        if (a != 0.0) atomicAdd(&g_acc[0], a);
        if (c2 != 0.0) atomicAdd(&g_acc[1], c2);
        if (cp) atomicAdd(&g_numpos[b], cp);
    }
}

// ---------------- kernel 3: radix top-k selection + fused finalize ----------------
// grid: B blocks x 1024
__global__ void k_select(float* __restrict__ out, int P, int B) {
    int b = blockIdx.x;
    __shared__ unsigned int sv[MAXP];
    __shared__ int hist[2048];
    __shared__ int warpTot[32];
    __shared__ int s_ri[32];
    __shared__ double s_rd[32];
    __shared__ int s_sel;
    int tid = threadIdx.x, nt = blockDim.x;
    int lane = tid & 31, wid = tid >> 5;

    for (int i = tid; i < P; i += nt)
        sv[i] = __float_as_uint(g_lossc[(size_t)b * P + i]);

    int npos = g_numpos[b];
    int k = 3 * npos;
    if (k > P - 1) k = P - 1;
    __syncthreads();

    if (k > 0) {
        unsigned int prefix = 0;
        int kk = k;
        const int bitsArr[3] = {11, 11, 10};
        const int shiftArr[3] = {21, 10, 0};
        int iters = (P + nt - 1) / nt;

        for (int r = 0; r < 3; r++) {
            int bits = bitsArr[r], shift = shiftArr[r];
            int nb = 1 << bits;
            bool pair = (nb == 2048);
            for (int i = tid; i < nb; i += nt) hist[i] = 0;
            if (tid == 0) s_sel = 0;
            __syncthreads();

            // histogram (warp-aggregated)
            for (int j = 0; j < iters; j++) {
                int i = tid + j * nt;
                bool valid = (i < P);
                unsigned int v = valid ? sv[i] : 0u;
                unsigned int hi = (r == 0) ? 0u : (v >> (shift + bits));
                valid = valid && (hi == prefix);
                unsigned int bm = __ballot_sync(0xFFFFFFFFu, valid);
                if (valid) {
                    int bin = (v >> shift) & (nb - 1);
                    unsigned int mm = __match_any_sync(bm, bin);
                    if (lane == __ffs(mm) - 1) atomicAdd(&hist[bin], __popc(mm));
                }
            }
            __syncthreads();

            // hierarchical suffix scan (shuffles + 2 barriers)
            int h0 = 0, h1 = 0, v;
            if (pair) { h0 = hist[2 * tid]; h1 = hist[2 * tid + 1]; v = h0 + h1; }
            else      { h0 = (tid < nb) ? hist[tid] : 0; v = h0; }
            int sIncl = warpSufI(v);                  // suffix within warp
            if (lane == 0) warpTot[wid] = sIncl;      // warp total
            __syncthreads();
            if (wid == 0) {
                int t = warpTot[lane];
                int ws = warpSufI(t);                 // inclusive suffix of totals
                warpTot[lane] = ws - t;               // exclusive (higher warps)
            }
            __syncthreads();
            int E = (sIncl - v) + warpTot[wid];       // sum over threads > tid
            int cand = -1;
            if (pair) {
                int suf0 = E + v, suf1 = E + h1;
                hist[2 * tid] = suf0; hist[2 * tid + 1] = suf1;
                if (suf1 >= kk) cand = 2 * tid + 1;
                else if (suf0 >= kk) cand = 2 * tid;
            } else if (tid < nb) {
                int suf0 = E + v;
                hist[tid] = suf0;
                if (suf0 >= kk) cand = tid;
            }
            if (cand >= 0) atomicMax(&s_sel, cand);
            __syncthreads();
            int d = s_sel;
            int above = (d + 1 < nb) ? hist[d + 1] : 0;
            kk -= above;
            prefix = (prefix << bits) | (unsigned int)d;
            __syncthreads();
        }

        unsigned int T = prefix;
        int c1 = 0;
        double s1 = 0.0;
        for (int i = tid; i < P; i += nt) {
            unsigned int v = sv[i];
            if (v > T) { c1++; s1 += (double)__uint_as_float(v); }
        }
        c1 = blockSumI(c1, s_ri);
        s1 = blockSumD(s1, s_rd);
        if (tid == 0)
            atomicAdd(&g_acc[2], s1 + (double)(k - c1) * (double)__uint_as_float(T));
    }

    // fused finalize: last block writes output
    if (tid == 0) {
        __threadfence();
        if (atomicAdd(&g_done, 1) == (int)gridDim.x - 1) {
            long long N = 0;
            for (int bb = 0; bb < B; bb++) N += g_numpos[bb];
            double Nd = (double)N;
            out[0] = (float)(g_acc[0] / Nd);
            out[1] = (float)((g_acc[1] + g_acc[2]) / Nd);
        }
    }
}

// ---------------- launch ----------------
extern "C" void kernel_launch(void* const* d_in, const int* in_sizes, int n_in,
                              void* d_out, int out_size) {
    const float* conf   = (const float*)d_in[0];
    const float* loc    = (const float*)d_in[1];
    const float* priors = (const float*)d_in[2];
    const float* labels = (const float*)d_in[3];
    const int*   obj    = (const int*)d_in[4];

    int P = in_sizes[2] / 4;
    int B = in_sizes[4];
    int NMAX = in_sizes[3] / (B * 5);

    k_init<<<(B * NMAX + 255) / 256, 256>>>(B, NMAX);

    dim3 gm((P + 255) / 256, B);
    k_match<<<gm, 256>>>(priors, labels, obj, P, NMAX);

    dim3 gl((P + 255) / 256, B);
    k_loss<21><<<gl, 128>>>(conf, loc, priors, labels, P, NMAX);

    k_select<<<B, 1024>>>((float*)d_out, P, B);
}